// round 14
// baseline (speedup 1.0000x reference)
#include <cuda_runtime.h>
#include <cuda_fp16.h>
#include <math.h>
#include <stdint.h>

// Problem constants
#define TOK   2048          // B*S
#define SEQ   1024
#define DM    768
#define DFF   3072
#define NH    12
#define HDIM  64
#define NV    32000
#define NL    6
#define QKVS  (3 * DM)      // 2304

typedef __half f16;

// -------------------- scratch (device globals; no allocation allowed) -----
__device__ __align__(16) float g_x  [TOK * DM];
__device__ __align__(16) f16   g_qkv[TOK * QKVS];
__device__ __align__(16) f16   g_h  [TOK * DM];
__device__ __align__(16) f16   g_at [TOK * DM];
__device__ __align__(16) f16   g_ff [TOK * DFF];
// converted weights [K,N] fp16
__device__ __align__(16) f16 g_wqkv[NL * DM * QKVS];
__device__ __align__(16) f16 g_wo  [NL * DM * DM];
__device__ __align__(16) f16 g_w1  [NL * DM * DFF];
__device__ __align__(16) f16 g_w2  [NL * DFF * DM];
__device__ __align__(16) f16 g_wout[DM * NV];

// -------------------- helpers ---------------------------------------------
__device__ __forceinline__ uint32_t cvta_smem(const void* p) {
    return (uint32_t)__cvta_generic_to_shared(p);
}
__device__ __forceinline__ void cp16(uint32_t s, const void* g) {
    asm volatile("cp.async.cg.shared.global [%0], [%1], 16;" :: "r"(s), "l"(g));
}
__device__ __forceinline__ void ldm_x4(uint32_t* r, uint32_t addr) {
    asm volatile("ldmatrix.sync.aligned.m8n8.x4.shared.b16 {%0,%1,%2,%3},[%4];"
                 : "=r"(r[0]), "=r"(r[1]), "=r"(r[2]), "=r"(r[3]) : "r"(addr));
}
__device__ __forceinline__ void ldm_x4_t(uint32_t* r, uint32_t addr) {
    asm volatile("ldmatrix.sync.aligned.m8n8.x4.trans.shared.b16 {%0,%1,%2,%3},[%4];"
                 : "=r"(r[0]), "=r"(r[1]), "=r"(r[2]), "=r"(r[3]) : "r"(addr));
}
__device__ __forceinline__ void mma_f16(float* c, const uint32_t* a, const uint32_t* b) {
    asm volatile(
        "mma.sync.aligned.m16n8k16.row.col.f32.f16.f16.f32 "
        "{%0,%1,%2,%3},{%4,%5,%6,%7},{%8,%9},{%0,%1,%2,%3};"
        : "+f"(c[0]), "+f"(c[1]), "+f"(c[2]), "+f"(c[3])
        : "r"(a[0]), "r"(a[1]), "r"(a[2]), "r"(a[3]), "r"(b[0]), "r"(b[1]));
}
__device__ __forceinline__ uint32_t pack_h2(float a, float b) {
    __half2 h = __floats2half2_rn(a, b);
    return *(uint32_t*)&h;
}

// -------------------- fused weight convert kernel ---------------------------
struct WCSeg {
    const float* src;
    f16* dst;
    int cols;
    int dstride;
    int cofs;
};
struct WCParams {
    WCSeg seg[7];
    unsigned start[8];   // prefix of 16-elem unit counts
};

__global__ void wconv_all(WCParams p, unsigned total16) {
    unsigned i = blockIdx.x * 256u + threadIdx.x;
    if (i >= total16) return;
    int s = 0;
#pragma unroll
    for (int j = 1; j < 7; j++) s += (i >= p.start[j]) ? 1 : 0;
    const float* src = p.seg[s].src;
    f16* dst = p.seg[s].dst;
    int cols = p.seg[s].cols;
    int dstride = p.seg[s].dstride;
    int cofs = p.seg[s].cofs;

    size_t e = (size_t)(i - p.start[s]) * 16;
    int r = (int)(e / (unsigned)cols), c = (int)(e - (size_t)r * cols);
    float4 v0 = __ldcs((const float4*)(src + e));
    float4 v1 = __ldcs((const float4*)(src + e + 4));
    float4 v2 = __ldcs((const float4*)(src + e + 8));
    float4 v3 = __ldcs((const float4*)(src + e + 12));
    size_t d = (size_t)r * dstride + cofs + c;
    f16 h[16];
    h[0]  = __float2half_rn(v0.x); h[1]  = __float2half_rn(v0.y);
    h[2]  = __float2half_rn(v0.z); h[3]  = __float2half_rn(v0.w);
    h[4]  = __float2half_rn(v1.x); h[5]  = __float2half_rn(v1.y);
    h[6]  = __float2half_rn(v1.z); h[7]  = __float2half_rn(v1.w);
    h[8]  = __float2half_rn(v2.x); h[9]  = __float2half_rn(v2.y);
    h[10] = __float2half_rn(v2.z); h[11] = __float2half_rn(v2.w);
    h[12] = __float2half_rn(v3.x); h[13] = __float2half_rn(v3.y);
    h[14] = __float2half_rn(v3.z); h[15] = __float2half_rn(v3.w);
    *(uint4*)(dst + d)     = *(uint4*)h;
    *(uint4*)(dst + d + 8) = *(uint4*)(h + 8);
}

// -------------------- embedding -------------------------------------------
__global__ void embed_kernel(const int* __restrict__ ctx,
                             const float* __restrict__ tok,
                             const float* __restrict__ pos) {
    int t = blockIdx.x;
    int token = ctx[t];
    int s = t & (SEQ - 1);
#pragma unroll
    for (int i = 0; i < 3; i++) {
        int d = threadIdx.x + i * 256;
        g_x[t * DM + d] = tok[token * DM + d] + pos[s * DM + d];
    }
}

// -------------------- layernorm -> fp16 (warp per row, no barriers) --------
__global__ __launch_bounds__(256)
void ln_half(const float* __restrict__ in,
             const float* __restrict__ gg,
             const float* __restrict__ bb,
             f16* __restrict__ out) {
    int warp = threadIdx.x >> 5, lane = threadIdx.x & 31;
    int row = blockIdx.x * 8 + warp;
    const float* x = in + (size_t)row * DM;

    float v[24];
    float s = 0.f, ss = 0.f;
#pragma unroll
    for (int i = 0; i < 6; i++) {
        float4 t = *(const float4*)(x + lane * 4 + i * 128);
        v[i*4+0] = t.x; v[i*4+1] = t.y; v[i*4+2] = t.z; v[i*4+3] = t.w;
        s  += t.x + t.y + t.z + t.w;
        ss += t.x*t.x + t.y*t.y + t.z*t.z + t.w*t.w;
    }
#pragma unroll
    for (int m = 16; m; m >>= 1) {
        s  += __shfl_xor_sync(0xffffffffu, s,  m);
        ss += __shfl_xor_sync(0xffffffffu, ss, m);
    }
    float mean = s * (1.0f / DM);
    float var  = ss * (1.0f / DM) - mean * mean;
    float inv  = rsqrtf(var + 1e-5f);

    f16* op = out + (size_t)row * DM;
#pragma unroll
    for (int i = 0; i < 6; i++) {
        int d = lane * 4 + i * 128;
        float4 gv = *(const float4*)(gg + d);
        float4 bv = *(const float4*)(bb + d);
        f16 h[4];
        h[0] = __float2half_rn((v[i*4+0] - mean) * inv * gv.x + bv.x);
        h[1] = __float2half_rn((v[i*4+1] - mean) * inv * gv.y + bv.y);
        h[2] = __float2half_rn((v[i*4+2] - mean) * inv * gv.z + bv.z);
        h[3] = __float2half_rn((v[i*4+3] - mean) * inv * gv.w + bv.w);
        *(uint2*)(op + d) = *(uint2*)h;
    }
}

// -------------------- fp16 tensor-core GEMM (BK=64, tiled BM x BN) ---------
__device__ __forceinline__ uint32_t swzA(int row, int kc) {   // kc 0..7
    return (uint32_t)(row * 128 + ((kc ^ (row & 7)) << 4));
}
template<int CR>   // chunks per B row: 16 (BN=128) or 8 (BN=64)
__device__ __forceinline__ uint32_t swzB(int k, int nc) {
    int c = (CR == 16) ? (((nc & 7) ^ (k & 7)) | (nc & 8)) : (nc ^ (k & 7));
    return (uint32_t)(k * (CR * 16) + (c << 4));
}

template<int BM, int BN, int OCC>
__global__ __launch_bounds__(256, OCC)
void hgemm(const f16* __restrict__ A, const f16* __restrict__ B,
           const float* __restrict__ bias, const float* __restrict__ res,
           float* __restrict__ C, f16* __restrict__ Oh,
           int N, int K, int relu) {
    constexpr int WM = BM / 2;
    constexpr int MT = WM / 16;
    constexpr int WN = BN / 4;
    constexpr int NT = WN / 8;
    constexpr int CR = BN / 8;
    constexpr int ABYTES = BM * 128;
    constexpr int BBYTES = 64 * BN * 2;
    constexpr int STAGE  = ABYTES + BBYTES;
    constexpr int NA = BM / 32;
    constexpr int NB = CR / 4;

    extern __shared__ char smc[];
    uint32_t sbase = cvta_smem(smc);

    int tid  = threadIdx.x;
    int lane = tid & 31;
    int warp = tid >> 5;
    int wm = warp >> 2;
    int wn = warp & 3;
    int g  = lane >> 2;
    int tg = lane & 3;
    int bm = blockIdx.x, bn = blockIdx.y;

    float acc[MT][NT][4];
#pragma unroll
    for (int mi = 0; mi < MT; mi++)
#pragma unroll
        for (int ni = 0; ni < NT; ni++)
#pragma unroll
            for (int j = 0; j < 4; j++) acc[mi][ni][j] = 0.f;

#define LOADSTAGE(IT)                                                         \
    {                                                                         \
        int _it = (IT);                                                       \
        uint32_t st = sbase + (_it % 3) * STAGE;                              \
        _Pragma("unroll")                                                     \
        for (int u = 0; u < NA; u++) {                                        \
            int cu = tid + u * 256;                                           \
            int arow = cu >> 3, akc = cu & 7;                                 \
            uint32_t so = st + swzA(arow, akc);                               \
            size_t go = (size_t)(bm * BM + arow) * K + _it * 64 + akc * 8;    \
            cp16(so, A + go);                                                 \
        }                                                                     \
        _Pragma("unroll")                                                     \
        for (int u = 0; u < NB; u++) {                                        \
            int cu = tid + u * 256;                                           \
            int bk = cu / CR, bnc = cu % CR;                                  \
            uint32_t so = st + ABYTES + swzB<CR>(bk, bnc);                    \
            size_t go = (size_t)(_it * 64 + bk) * N + bn * BN + bnc * 8;      \
            cp16(so, B + go);                                                 \
        }                                                                     \
    }

    int nIter = K >> 6;
    LOADSTAGE(0); asm volatile("cp.async.commit_group;");
    LOADSTAGE(1); asm volatile("cp.async.commit_group;");

    int a_lrow = wm * WM + (lane & 15);
    int a_koff = (lane >> 4) & 1;
    int b_lk   = lane & 15;
    int b_noff = (lane >> 4) & 1;

    for (int it = 0; it < nIter; it++) {
        asm volatile("cp.async.wait_group 1;");
        __syncthreads();
        uint32_t sb = sbase + (it % 3) * STAGE;

#pragma unroll
        for (int k16 = 0; k16 < 4; k16++) {
            uint32_t Af[MT][4], Bf[NT][2];
            int kc = k16 * 2 + a_koff;
#pragma unroll
            for (int mi = 0; mi < MT; mi++)
                ldm_x4(Af[mi], sb + swzA(a_lrow + mi * 16, kc));
            int kk = k16 * 16 + b_lk;
#pragma unroll
            for (int p = 0; p < NT / 2; p++) {
                uint32_t r4[4];
                ldm_x4_t(r4, sb + ABYTES + swzB<CR>(kk, wn * NT + 2 * p + b_noff));
                Bf[p*2][0] = r4[0]; Bf[p*2][1] = r4[1];
                Bf[p*2+1][0] = r4[2]; Bf[p*2+1][1] = r4[3];
            }
#pragma unroll
            for (int mi = 0; mi < MT; mi++)
#pragma unroll
                for (int ni = 0; ni < NT; ni++) mma_f16(acc[mi][ni], Af[mi], Bf[ni]);
        }

        if (it + 2 < nIter) LOADSTAGE(it + 2);
        asm volatile("cp.async.commit_group;");
    }
#undef LOADSTAGE

#pragma unroll
    for (int mi = 0; mi < MT; mi++) {
        int row0 = bm * BM + wm * WM + mi * 16 + g;
#pragma unroll
        for (int ni = 0; ni < NT; ni++) {
            int col = bn * BN + wn * WN + ni * 8 + 2 * tg;
            float b0 = 0.f, b1 = 0.f;
            if (bias) { b0 = bias[col]; b1 = bias[col + 1]; }
#pragma unroll
            for (int half = 0; half < 2; half++) {
                int row = row0 + half * 8;
                float v0 = acc[mi][ni][half * 2 + 0] + b0;
                float v1 = acc[mi][ni][half * 2 + 1] + b1;
                if (relu) { v0 = fmaxf(v0, 0.f); v1 = fmaxf(v1, 0.f); }
                size_t idx = (size_t)row * N + col;
                if (Oh) {
                    *(__half2*)(Oh + idx) =
                        __half2(__float2half_rn(v0), __float2half_rn(v1));
                } else {
                    if (res) {
                        float2 r2 = *(const float2*)(res + idx);
                        v0 += r2.x; v1 += r2.y;
                    }
                    *(float2*)(C + idx) = make_float2(v0, v1);
                }
            }
        }
    }
}

// -------------------- fp16 tensor-core flash attention ----------------------
#define AQ_BYTES 8192
#define AKV_STAGE 16384
#define ATT_SMEM (AQ_BYTES + 3 * AKV_STAGE)

__device__ __forceinline__ uint32_t swzR(int row, int c) {   // 128B rows
    return (uint32_t)(row * 128 + ((c ^ (row & 7)) << 4));
}

__global__ __launch_bounds__(128)
void attn_f16(const f16* __restrict__ QKV, f16* __restrict__ O) {
    extern __shared__ char smc[];
    uint32_t sb = cvta_smem(smc);

    int qt = gridDim.x - 1 - blockIdx.x;   // heavy tiles first
    int h = blockIdx.y, b = blockIdx.z;
    int tid = threadIdx.x, lane = tid & 31, warp = tid >> 5;
    int g = lane >> 2, tg = lane & 3;
    int wrow = warp * 16;
    int nT = qt + 1;

    const f16* Qg = QKV + (size_t)(b * SEQ + qt * 64) * QKVS + h * HDIM;

#define LOADQ()                                                               \
    {                                                                         \
        _Pragma("unroll")                                                     \
        for (int u = 0; u < 4; u++) {                                         \
            int idx = tid + u * 128;                                          \
            int row = idx >> 3, c = idx & 7;                                  \
            cp16(sb + swzR(row, c), Qg + (size_t)row * QKVS + c * 8);         \
        }                                                                     \
    }
#define LOADKV(SLOT, KT)                                                      \
    {                                                                         \
        uint32_t st = sb + AQ_BYTES + ((SLOT) % 3) * AKV_STAGE;               \
        const f16* Kg = QKV + (size_t)(b * SEQ + (KT) * 64) * QKVS            \
                        + DM + h * HDIM;                                      \
        _Pragma("unroll")                                                     \
        for (int u = 0; u < 4; u++) {                                         \
            int idx = tid + u * 128;                                          \
            int row = idx >> 3, c = idx & 7;                                  \
            uint32_t so = st + swzR(row, c);                                  \
            size_t go = (size_t)row * QKVS + c * 8;                           \
            cp16(so, Kg + go);                                                \
            cp16(so + 8192, Kg + DM + go);                                    \
        }                                                                     \
    }

    LOADQ(); LOADKV(0, 0);
    asm volatile("cp.async.commit_group;");
    if (1 < nT) LOADKV(1, 1);
    asm volatile("cp.async.commit_group;");

    float o[8][4];
#pragma unroll
    for (int nt = 0; nt < 8; nt++)
#pragma unroll
        for (int j = 0; j < 4; j++) o[nt][j] = 0.f;
    float m[2] = {-INFINITY, -INFINITY}, l[2] = {0.f, 0.f};
    uint32_t qf[4][4];

    for (int kt = 0; kt < nT; kt++) {
        asm volatile("cp.async.wait_group 1;");
        __syncthreads();

        if (kt == 0) {
#pragma unroll
            for (int i = 0; i < 4; i++) {
                int row = wrow + (lane & 15);
                int c = 2 * i + (lane >> 4);
                ldm_x4(qf[i], sb + swzR(row, c));
            }
        }

        if (kt + 2 < nT) LOADKV(kt + 2, kt + 2);
        asm volatile("cp.async.commit_group;");

        uint32_t kb = sb + AQ_BYTES + (kt % 3) * AKV_STAGE;
        float s[8][4];
#pragma unroll
        for (int nt = 0; nt < 8; nt++)
#pragma unroll
            for (int j = 0; j < 4; j++) s[nt][j] = 0.f;

#pragma unroll
        for (int ntp = 0; ntp < 4; ntp++) {
            int krow = ntp * 16 + (lane & 7) + ((lane >> 4) << 3);
#pragma unroll
            for (int i = 0; i < 4; i++) {
                uint32_t r4[4];
                int c = 2 * i + ((lane >> 3) & 1);
                ldm_x4(r4, kb + swzR(krow, c));
                mma_f16(s[2 * ntp],     qf[i], r4);
                mma_f16(s[2 * ntp + 1], qf[i], r4 + 2);
            }
        }

#pragma unroll
        for (int nt = 0; nt < 8; nt++)
#pragma unroll
            for (int j = 0; j < 4; j++) s[nt][j] *= 0.125f;
        if (kt == qt) {
            int rA = wrow + g, rB = rA + 8;
#pragma unroll
            for (int nt = 0; nt < 8; nt++) {
                int cc = nt * 8 + 2 * tg;
                if (cc     > rA) s[nt][0] = -1e30f;
                if (cc + 1 > rA) s[nt][1] = -1e30f;
                if (cc     > rB) s[nt][2] = -1e30f;
                if (cc + 1 > rB) s[nt][3] = -1e30f;
            }
        }

        float mxA = -1e30f, mxB = -1e30f;
#pragma unroll
        for (int nt = 0; nt < 8; nt++) {
            mxA = fmaxf(mxA, fmaxf(s[nt][0], s[nt][1]));
            mxB = fmaxf(mxB, fmaxf(s[nt][2], s[nt][3]));
        }
        mxA = fmaxf(mxA, __shfl_xor_sync(0xffffffffu, mxA, 1));
        mxA = fmaxf(mxA, __shfl_xor_sync(0xffffffffu, mxA, 2));
        mxB = fmaxf(mxB, __shfl_xor_sync(0xffffffffu, mxB, 1));
        mxB = fmaxf(mxB, __shfl_xor_sync(0xffffffffu, mxB, 2));
        float mnA = fmaxf(m[0], mxA), mnB = fmaxf(m[1], mxB);
        float fA = __expf(m[0] - mnA), fB = __expf(m[1] - mnB);
        float sA = 0.f, sB = 0.f;
#pragma unroll
        for (int nt = 0; nt < 8; nt++) {
            s[nt][0] = __expf(s[nt][0] - mnA);
            s[nt][1] = __expf(s[nt][1] - mnA);
            s[nt][2] = __expf(s[nt][2] - mnB);
            s[nt][3] = __expf(s[nt][3] - mnB);
            sA += s[nt][0] + s[nt][1];
            sB += s[nt][2] + s[nt][3];
        }
        sA += __shfl_xor_sync(0xffffffffu, sA, 1);
        sA += __shfl_xor_sync(0xffffffffu, sA, 2);
        sB += __shfl_xor_sync(0xffffffffu, sB, 1);
        sB += __shfl_xor_sync(0xffffffffu, sB, 2);
        l[0] = l[0] * fA + sA; m[0] = mnA;
        l[1] = l[1] * fB + sB; m[1] = mnB;
#pragma unroll
        for (int nt = 0; nt < 8; nt++) {
            o[nt][0] *= fA; o[nt][1] *= fA;
            o[nt][2] *= fB; o[nt][3] *= fB;
        }

        uint32_t pk[4][4];
#pragma unroll
        for (int i = 0; i < 4; i++) {
            pk[i][0] = pack_h2(s[2*i][0],   s[2*i][1]);
            pk[i][1] = pack_h2(s[2*i][2],   s[2*i][3]);
            pk[i][2] = pack_h2(s[2*i+1][0], s[2*i+1][1]);
            pk[i][3] = pack_h2(s[2*i+1][2], s[2*i+1][3]);
        }

        uint32_t vb = kb + 8192;
#pragma unroll
        for (int i = 0; i < 4; i++) {
            int vrow = i * 16 + (lane & 15);
#pragma unroll
            for (int hdp = 0; hdp < 4; hdp++) {
                uint32_t r4[4];
                int c = 2 * hdp + (lane >> 4);
                ldm_x4_t(r4, vb + swzR(vrow, c));
                mma_f16(o[2 * hdp],     pk[i], r4);
                mma_f16(o[2 * hdp + 1], pk[i], r4 + 2);
            }
        }
    }
#undef LOADQ
#undef LOADKV

    float iA = 1.f / l[0], iB = 1.f / l[1];
    size_t rowA = (size_t)(b * SEQ + qt * 64 + wrow + g);
    f16* oA = O + rowA * DM + h * HDIM;
    f16* oB = oA + (size_t)8 * DM;
#pragma unroll
    for (int nt = 0; nt < 8; nt++) {
        int cc = nt * 8 + 2 * tg;
        *(__half2*)(oA + cc) = __floats2half2_rn(o[nt][0] * iA, o[nt][1] * iA);
        *(__half2*)(oB + cc) = __floats2half2_rn(o[nt][2] * iB, o[nt][3] * iB);
    }
}

// -------------------- host orchestration ----------------------------------
#define SM128   (3 * (128 * 128 + 16384))   // 98304
#define SM6464  (3 * (64 * 128 + 8192))     // 49152
#define SM64128 (3 * (64 * 128 + 16384))    // 73728

extern "C" void kernel_launch(void* const* d_in, const int* in_sizes, int n_in,
                              void* d_out, int out_size) {
    const int*   ctx  = (const int*)  d_in[0];
    const float* tok  = (const float*)d_in[1];
    const float* pos  = (const float*)d_in[2];
    const float* Wq   = (const float*)d_in[3];
    const float* Wk   = (const float*)d_in[4];
    const float* Wv   = (const float*)d_in[5];
    const float* Wo   = (const float*)d_in[6];
    const float* bo   = (const float*)d_in[7];
    const float* ln1g = (const float*)d_in[8];
    const float* ln1b = (const float*)d_in[9];
    const float* W1   = (const float*)d_in[10];
    const float* b1   = (const float*)d_in[11];
    const float* W2   = (const float*)d_in[12];
    const float* b2   = (const float*)d_in[13];
    const float* ln2g = (const float*)d_in[14];
    const float* ln2b = (const float*)d_in[15];
    const float* lnfg = (const float*)d_in[16];
    const float* lnfb = (const float*)d_in[17];
    const float* Wout = (const float*)d_in[18];
    const float* bout = (const float*)d_in[19];

    float* px;
    f16 *pqkv, *ph, *pat, *pff;
    f16 *pwqkv, *pwo, *pw1, *pw2, *pwout;
    cudaGetSymbolAddress((void**)&px,   g_x);
    cudaGetSymbolAddress((void**)&pqkv, g_qkv);
    cudaGetSymbolAddress((void**)&ph,   g_h);
    cudaGetSymbolAddress((void**)&pat,  g_at);
    cudaGetSymbolAddress((void**)&pff,  g_ff);
    cudaGetSymbolAddress((void**)&pwqkv, g_wqkv);
    cudaGetSymbolAddress((void**)&pwo,   g_wo);
    cudaGetSymbolAddress((void**)&pw1,   g_w1);
    cudaGetSymbolAddress((void**)&pw2,   g_w2);
    cudaGetSymbolAddress((void**)&pwout, g_wout);

    cudaFuncSetAttribute(attn_f16,
                         cudaFuncAttributeMaxDynamicSharedMemorySize, ATT_SMEM);
    cudaFuncSetAttribute((const void*)hgemm<128, 128, 2>,
                         cudaFuncAttributeMaxDynamicSharedMemorySize, SM128);
    cudaFuncSetAttribute((const void*)hgemm<64, 64, 3>,
                         cudaFuncAttributeMaxDynamicSharedMemorySize, SM6464);
    cudaFuncSetAttribute((const void*)hgemm<64, 128, 3>,
                         cudaFuncAttributeMaxDynamicSharedMemorySize, SM64128);

    // ---- fused weight conversion (single launch) ----
    {
        WCParams p;
        unsigned nQ  = (unsigned)(NL * DM * DM / 16);     // per Q/K/V/Wo
        unsigned nF  = (unsigned)(NL * DM * DFF / 16);    // per W1/W2
        unsigned nO  = (unsigned)(DM * NV / 16);          // Wout
        p.seg[0] = {Wq,   pwqkv, DM,  QKVS, 0};
        p.seg[1] = {Wk,   pwqkv, DM,  QKVS, DM};
        p.seg[2] = {Wv,   pwqkv, DM,  QKVS, 2 * DM};
        p.seg[3] = {Wo,   pwo,   DM,  DM,   0};
        p.seg[4] = {W1,   pw1,   DFF, DFF,  0};
        p.seg[5] = {W2,   pw2,   DM,  DM,   0};
        p.seg[6] = {Wout, pwout, NV,  NV,   0};
        unsigned counts[7] = {nQ, nQ, nQ, nQ, nF, nF, nO};
        unsigned acc = 0;
        for (int i = 0; i < 7; i++) { p.start[i] = acc; acc += counts[i]; }
        p.start[7] = acc;
        wconv_all<<<(acc + 255) / 256, 256>>>(p, acc);
    }

    embed_kernel<<<TOK, 256>>>(ctx, tok, pos);

    for (int l = 0; l < NL; l++) {
        size_t oqkv = (size_t)l * DM * QKVS;
        size_t owo  = (size_t)l * DM * DM;
        size_t ow1  = (size_t)l * DM * DFF;
        size_t ow2  = (size_t)l * DFF * DM;

        ln_half<<<TOK / 8, 256>>>(px, ln1g + l * DM, ln1b + l * DM, ph);
        hgemm<128, 128, 2><<<dim3(16, 18), 256, SM128>>>(
            ph, pwqkv + oqkv, nullptr, nullptr, nullptr, pqkv, QKVS, DM, 0);
        attn_f16<<<dim3(SEQ / 64, NH, 2), 128, ATT_SMEM>>>(pqkv, pat);
        hgemm<64, 64, 3><<<dim3(32, 12), 256, SM6464>>>(
            pat, pwo + owo, bo + l * DM, px, px, nullptr, DM, DM, 0);
        ln_half<<<TOK / 8, 256>>>(px, ln2g + l * DM, ln2b + l * DM, ph);
        hgemm<64, 128, 3><<<dim3(32, 24), 256, SM64128>>>(
            ph, pw1 + ow1, b1 + (size_t)l * DFF, nullptr, nullptr, pff,
            DFF, DM, 1);
        hgemm<64, 64, 3><<<dim3(32, 12), 256, SM6464>>>(
            pff, pw2 + ow2, b2 + l * DM, px, px, nullptr, DM, DFF, 0);
    }

    ln_half<<<TOK / 8, 256>>>(px, lnfg, lnfb, ph);
    hgemm<128, 128, 2><<<dim3(16, 250), 256, SM128>>>(
        ph, pwout, bout, nullptr, (float*)d_out, nullptr, NV, DM, 0);
}

// round 15
// speedup vs baseline: 1.0203x; 1.0203x over previous
#include <cuda_runtime.h>
#include <cuda_fp16.h>
#include <math.h>
#include <stdint.h>

// Problem constants
#define TOK   2048          // B*S
#define SEQ   1024
#define DM    768
#define DFF   3072
#define NH    12
#define HDIM  64
#define NV    32000
#define NL    6
#define QKVS  (3 * DM)      // 2304

typedef __half f16;

// -------------------- scratch (device globals; no allocation allowed) -----
__device__ __align__(16) float g_x  [TOK * DM];
__device__ __align__(16) f16   g_qkv[TOK * QKVS];
__device__ __align__(16) f16   g_h  [TOK * DM];
__device__ __align__(16) f16   g_at [TOK * DM];
__device__ __align__(16) f16   g_ff [TOK * DFF];
// converted weights [K,N] fp16
__device__ __align__(16) f16 g_wqkv[NL * DM * QKVS];
__device__ __align__(16) f16 g_wo  [NL * DM * DM];
__device__ __align__(16) f16 g_w1  [NL * DM * DFF];
__device__ __align__(16) f16 g_w2  [NL * DFF * DM];
__device__ __align__(16) f16 g_wout[DM * NV];

// -------------------- helpers ---------------------------------------------
__device__ __forceinline__ uint32_t cvta_smem(const void* p) {
    return (uint32_t)__cvta_generic_to_shared(p);
}
__device__ __forceinline__ void cp16(uint32_t s, const void* g) {
    asm volatile("cp.async.cg.shared.global [%0], [%1], 16;" :: "r"(s), "l"(g));
}
__device__ __forceinline__ void ldm_x4(uint32_t* r, uint32_t addr) {
    asm volatile("ldmatrix.sync.aligned.m8n8.x4.shared.b16 {%0,%1,%2,%3},[%4];"
                 : "=r"(r[0]), "=r"(r[1]), "=r"(r[2]), "=r"(r[3]) : "r"(addr));
}
__device__ __forceinline__ void ldm_x4_t(uint32_t* r, uint32_t addr) {
    asm volatile("ldmatrix.sync.aligned.m8n8.x4.trans.shared.b16 {%0,%1,%2,%3},[%4];"
                 : "=r"(r[0]), "=r"(r[1]), "=r"(r[2]), "=r"(r[3]) : "r"(addr));
}
__device__ __forceinline__ void mma_f16(float* c, const uint32_t* a, const uint32_t* b) {
    asm volatile(
        "mma.sync.aligned.m16n8k16.row.col.f32.f16.f16.f32 "
        "{%0,%1,%2,%3},{%4,%5,%6,%7},{%8,%9},{%0,%1,%2,%3};"
        : "+f"(c[0]), "+f"(c[1]), "+f"(c[2]), "+f"(c[3])
        : "r"(a[0]), "r"(a[1]), "r"(a[2]), "r"(a[3]), "r"(b[0]), "r"(b[1]));
}
__device__ __forceinline__ uint32_t pack_h2(float a, float b) {
    __half2 h = __floats2half2_rn(a, b);
    return *(uint32_t*)&h;
}

// -------------------- fused weight convert kernel ---------------------------
struct WCSeg {
    const float* src;
    f16* dst;
    int cols;
    int dstride;
    int cofs;
};
struct WCParams {
    WCSeg seg[7];
    unsigned start[8];   // prefix of 16-elem unit counts
};

__global__ void wconv_all(WCParams p, unsigned total16) {
    unsigned i = blockIdx.x * 256u + threadIdx.x;
    if (i >= total16) return;
    int s = 0;
#pragma unroll
    for (int j = 1; j < 7; j++) s += (i >= p.start[j]) ? 1 : 0;
    const float* src = p.seg[s].src;
    f16* dst = p.seg[s].dst;
    int cols = p.seg[s].cols;
    int dstride = p.seg[s].dstride;
    int cofs = p.seg[s].cofs;

    size_t e = (size_t)(i - p.start[s]) * 16;
    int r = (int)(e / (unsigned)cols), c = (int)(e - (size_t)r * cols);
    float4 v0 = __ldcs((const float4*)(src + e));
    float4 v1 = __ldcs((const float4*)(src + e + 4));
    float4 v2 = __ldcs((const float4*)(src + e + 8));
    float4 v3 = __ldcs((const float4*)(src + e + 12));
    size_t d = (size_t)r * dstride + cofs + c;
    f16 h[16];
    h[0]  = __float2half_rn(v0.x); h[1]  = __float2half_rn(v0.y);
    h[2]  = __float2half_rn(v0.z); h[3]  = __float2half_rn(v0.w);
    h[4]  = __float2half_rn(v1.x); h[5]  = __float2half_rn(v1.y);
    h[6]  = __float2half_rn(v1.z); h[7]  = __float2half_rn(v1.w);
    h[8]  = __float2half_rn(v2.x); h[9]  = __float2half_rn(v2.y);
    h[10] = __float2half_rn(v2.z); h[11] = __float2half_rn(v2.w);
    h[12] = __float2half_rn(v3.x); h[13] = __float2half_rn(v3.y);
    h[14] = __float2half_rn(v3.z); h[15] = __float2half_rn(v3.w);
    *(uint4*)(dst + d)     = *(uint4*)h;
    *(uint4*)(dst + d + 8) = *(uint4*)(h + 8);
}

// -------------------- embedding -------------------------------------------
__global__ void embed_kernel(const int* __restrict__ ctx,
                             const float* __restrict__ tok,
                             const float* __restrict__ pos) {
    int t = blockIdx.x;
    int token = ctx[t];
    int s = t & (SEQ - 1);
#pragma unroll
    for (int i = 0; i < 3; i++) {
        int d = threadIdx.x + i * 256;
        g_x[t * DM + d] = tok[token * DM + d] + pos[s * DM + d];
    }
}

// -------------------- layernorm -> fp16 (warp per row, no barriers) --------
__global__ __launch_bounds__(256)
void ln_half(const float* __restrict__ in,
             const float* __restrict__ gg,
             const float* __restrict__ bb,
             f16* __restrict__ out) {
    int warp = threadIdx.x >> 5, lane = threadIdx.x & 31;
    int row = blockIdx.x * 8 + warp;
    const float* x = in + (size_t)row * DM;

    float v[24];
    float s = 0.f, ss = 0.f;
#pragma unroll
    for (int i = 0; i < 6; i++) {
        float4 t = *(const float4*)(x + lane * 4 + i * 128);
        v[i*4+0] = t.x; v[i*4+1] = t.y; v[i*4+2] = t.z; v[i*4+3] = t.w;
        s  += t.x + t.y + t.z + t.w;
        ss += t.x*t.x + t.y*t.y + t.z*t.z + t.w*t.w;
    }
#pragma unroll
    for (int m = 16; m; m >>= 1) {
        s  += __shfl_xor_sync(0xffffffffu, s,  m);
        ss += __shfl_xor_sync(0xffffffffu, ss, m);
    }
    float mean = s * (1.0f / DM);
    float var  = ss * (1.0f / DM) - mean * mean;
    float inv  = rsqrtf(var + 1e-5f);

    f16* op = out + (size_t)row * DM;
#pragma unroll
    for (int i = 0; i < 6; i++) {
        int d = lane * 4 + i * 128;
        float4 gv = *(const float4*)(gg + d);
        float4 bv = *(const float4*)(bb + d);
        f16 h[4];
        h[0] = __float2half_rn((v[i*4+0] - mean) * inv * gv.x + bv.x);
        h[1] = __float2half_rn((v[i*4+1] - mean) * inv * gv.y + bv.y);
        h[2] = __float2half_rn((v[i*4+2] - mean) * inv * gv.z + bv.z);
        h[3] = __float2half_rn((v[i*4+3] - mean) * inv * gv.w + bv.w);
        *(uint2*)(op + d) = *(uint2*)h;
    }
}

// -------------------- fp16 tensor-core GEMM (BK=64, tiled BM x BN) ---------
__device__ __forceinline__ uint32_t swzA(int row, int kc) {   // kc 0..7
    return (uint32_t)(row * 128 + ((kc ^ (row & 7)) << 4));
}
template<int CR>   // chunks per B row: 16 (BN=128) or 8 (BN=64)
__device__ __forceinline__ uint32_t swzB(int k, int nc) {
    int c = (CR == 16) ? (((nc & 7) ^ (k & 7)) | (nc & 8)) : (nc ^ (k & 7));
    return (uint32_t)(k * (CR * 16) + (c << 4));
}

template<int BM, int BN, int OCC>
__global__ __launch_bounds__(256, OCC)
void hgemm(const f16* __restrict__ A, const f16* __restrict__ B,
           const float* __restrict__ bias, const float* __restrict__ res,
           float* __restrict__ C, f16* __restrict__ Oh,
           int N, int K, int relu) {
    constexpr int WM = BM / 2;
    constexpr int MT = WM / 16;
    constexpr int WN = BN / 4;
    constexpr int NT = WN / 8;
    constexpr int CR = BN / 8;
    constexpr int ABYTES = BM * 128;
    constexpr int BBYTES = 64 * BN * 2;
    constexpr int STAGE  = ABYTES + BBYTES;
    constexpr int NA = BM / 32;
    constexpr int NB = CR / 4;

    extern __shared__ char smc[];
    uint32_t sbase = cvta_smem(smc);

    int tid  = threadIdx.x;
    int lane = tid & 31;
    int warp = tid >> 5;
    int wm = warp >> 2;
    int wn = warp & 3;
    int g  = lane >> 2;
    int tg = lane & 3;
    int bm = blockIdx.x, bn = blockIdx.y;

    float acc[MT][NT][4];
#pragma unroll
    for (int mi = 0; mi < MT; mi++)
#pragma unroll
        for (int ni = 0; ni < NT; ni++)
#pragma unroll
            for (int j = 0; j < 4; j++) acc[mi][ni][j] = 0.f;

#define LOADSTAGE(IT)                                                         \
    {                                                                         \
        int _it = (IT);                                                       \
        uint32_t st = sbase + (_it % 3) * STAGE;                              \
        _Pragma("unroll")                                                     \
        for (int u = 0; u < NA; u++) {                                        \
            int cu = tid + u * 256;                                           \
            int arow = cu >> 3, akc = cu & 7;                                 \
            uint32_t so = st + swzA(arow, akc);                               \
            size_t go = (size_t)(bm * BM + arow) * K + _it * 64 + akc * 8;    \
            cp16(so, A + go);                                                 \
        }                                                                     \
        _Pragma("unroll")                                                     \
        for (int u = 0; u < NB; u++) {                                        \
            int cu = tid + u * 256;                                           \
            int bk = cu / CR, bnc = cu % CR;                                  \
            uint32_t so = st + ABYTES + swzB<CR>(bk, bnc);                    \
            size_t go = (size_t)(_it * 64 + bk) * N + bn * BN + bnc * 8;      \
            cp16(so, B + go);                                                 \
        }                                                                     \
    }

    int nIter = K >> 6;
    LOADSTAGE(0); asm volatile("cp.async.commit_group;");
    LOADSTAGE(1); asm volatile("cp.async.commit_group;");

    int a_lrow = wm * WM + (lane & 15);
    int a_koff = (lane >> 4) & 1;
    int b_lk   = lane & 15;
    int b_noff = (lane >> 4) & 1;

    for (int it = 0; it < nIter; it++) {
        asm volatile("cp.async.wait_group 1;");
        __syncthreads();
        uint32_t sb = sbase + (it % 3) * STAGE;

#pragma unroll
        for (int k16 = 0; k16 < 4; k16++) {
            uint32_t Af[MT][4], Bf[NT][2];
            int kc = k16 * 2 + a_koff;
#pragma unroll
            for (int mi = 0; mi < MT; mi++)
                ldm_x4(Af[mi], sb + swzA(a_lrow + mi * 16, kc));
            int kk = k16 * 16 + b_lk;
#pragma unroll
            for (int p = 0; p < NT / 2; p++) {
                uint32_t r4[4];
                ldm_x4_t(r4, sb + ABYTES + swzB<CR>(kk, wn * NT + 2 * p + b_noff));
                Bf[p*2][0] = r4[0]; Bf[p*2][1] = r4[1];
                Bf[p*2+1][0] = r4[2]; Bf[p*2+1][1] = r4[3];
            }
#pragma unroll
            for (int mi = 0; mi < MT; mi++)
#pragma unroll
                for (int ni = 0; ni < NT; ni++) mma_f16(acc[mi][ni], Af[mi], Bf[ni]);
        }

        if (it + 2 < nIter) LOADSTAGE(it + 2);
        asm volatile("cp.async.commit_group;");
    }
#undef LOADSTAGE

#pragma unroll
    for (int mi = 0; mi < MT; mi++) {
        int row0 = bm * BM + wm * WM + mi * 16 + g;
#pragma unroll
        for (int ni = 0; ni < NT; ni++) {
            int col = bn * BN + wn * WN + ni * 8 + 2 * tg;
            float b0 = 0.f, b1 = 0.f;
            if (bias) { b0 = bias[col]; b1 = bias[col + 1]; }
#pragma unroll
            for (int half = 0; half < 2; half++) {
                int row = row0 + half * 8;
                float v0 = acc[mi][ni][half * 2 + 0] + b0;
                float v1 = acc[mi][ni][half * 2 + 1] + b1;
                if (relu) { v0 = fmaxf(v0, 0.f); v1 = fmaxf(v1, 0.f); }
                size_t idx = (size_t)row * N + col;
                if (Oh) {
                    *(__half2*)(Oh + idx) =
                        __half2(__float2half_rn(v0), __float2half_rn(v1));
                } else {
                    if (res) {
                        float2 r2 = *(const float2*)(res + idx);
                        v0 += r2.x; v1 += r2.y;
                    }
                    *(float2*)(C + idx) = make_float2(v0, v1);
                }
            }
        }
    }
}

// -------------------- fp16 tensor-core flash attention ----------------------
#define AQ_BYTES 8192
#define AKV_STAGE 16384
#define ATT_SMEM (AQ_BYTES + 3 * AKV_STAGE)

__device__ __forceinline__ uint32_t swzR(int row, int c) {   // 128B rows
    return (uint32_t)(row * 128 + ((c ^ (row & 7)) << 4));
}

__global__ __launch_bounds__(128)
void attn_f16(const f16* __restrict__ QKV, f16* __restrict__ O) {
    extern __shared__ char smc[];
    uint32_t sb = cvta_smem(smc);

    int qt = gridDim.x - 1 - blockIdx.x;   // heavy tiles first
    int h = blockIdx.y, b = blockIdx.z;
    int tid = threadIdx.x, lane = tid & 31, warp = tid >> 5;
    int g = lane >> 2, tg = lane & 3;
    int wrow = warp * 16;
    int nT = qt + 1;

    const f16* Qg = QKV + (size_t)(b * SEQ + qt * 64) * QKVS + h * HDIM;

#define LOADQ()                                                               \
    {                                                                         \
        _Pragma("unroll")                                                     \
        for (int u = 0; u < 4; u++) {                                         \
            int idx = tid + u * 128;                                          \
            int row = idx >> 3, c = idx & 7;                                  \
            cp16(sb + swzR(row, c), Qg + (size_t)row * QKVS + c * 8);         \
        }                                                                     \
    }
#define LOADKV(SLOT, KT)                                                      \
    {                                                                         \
        uint32_t st = sb + AQ_BYTES + ((SLOT) % 3) * AKV_STAGE;               \
        const f16* Kg = QKV + (size_t)(b * SEQ + (KT) * 64) * QKVS            \
                        + DM + h * HDIM;                                      \
        _Pragma("unroll")                                                     \
        for (int u = 0; u < 4; u++) {                                         \
            int idx = tid + u * 128;                                          \
            int row = idx >> 3, c = idx & 7;                                  \
            uint32_t so = st + swzR(row, c);                                  \
            size_t go = (size_t)row * QKVS + c * 8;                           \
            cp16(so, Kg + go);                                                \
            cp16(so + 8192, Kg + DM + go);                                    \
        }                                                                     \
    }

    LOADQ(); LOADKV(0, 0);
    asm volatile("cp.async.commit_group;");
    if (1 < nT) LOADKV(1, 1);
    asm volatile("cp.async.commit_group;");

    float o[8][4];
#pragma unroll
    for (int nt = 0; nt < 8; nt++)
#pragma unroll
        for (int j = 0; j < 4; j++) o[nt][j] = 0.f;
    float m[2] = {-INFINITY, -INFINITY}, l[2] = {0.f, 0.f};
    uint32_t qf[4][4];

    for (int kt = 0; kt < nT; kt++) {
        asm volatile("cp.async.wait_group 1;");
        __syncthreads();

        if (kt == 0) {
#pragma unroll
            for (int i = 0; i < 4; i++) {
                int row = wrow + (lane & 15);
                int c = 2 * i + (lane >> 4);
                ldm_x4(qf[i], sb + swzR(row, c));
            }
        }

        if (kt + 2 < nT) LOADKV(kt + 2, kt + 2);
        asm volatile("cp.async.commit_group;");

        uint32_t kb = sb + AQ_BYTES + (kt % 3) * AKV_STAGE;
        float s[8][4];
#pragma unroll
        for (int nt = 0; nt < 8; nt++)
#pragma unroll
            for (int j = 0; j < 4; j++) s[nt][j] = 0.f;

#pragma unroll
        for (int ntp = 0; ntp < 4; ntp++) {
            int krow = ntp * 16 + (lane & 7) + ((lane >> 4) << 3);
#pragma unroll
            for (int i = 0; i < 4; i++) {
                uint32_t r4[4];
                int c = 2 * i + ((lane >> 3) & 1);
                ldm_x4(r4, kb + swzR(krow, c));
                mma_f16(s[2 * ntp],     qf[i], r4);
                mma_f16(s[2 * ntp + 1], qf[i], r4 + 2);
            }
        }

#pragma unroll
        for (int nt = 0; nt < 8; nt++)
#pragma unroll
            for (int j = 0; j < 4; j++) s[nt][j] *= 0.125f;
        if (kt == qt) {
            int rA = wrow + g, rB = rA + 8;
#pragma unroll
            for (int nt = 0; nt < 8; nt++) {
                int cc = nt * 8 + 2 * tg;
                if (cc     > rA) s[nt][0] = -1e30f;
                if (cc + 1 > rA) s[nt][1] = -1e30f;
                if (cc     > rB) s[nt][2] = -1e30f;
                if (cc + 1 > rB) s[nt][3] = -1e30f;
            }
        }

        float mxA = -1e30f, mxB = -1e30f;
#pragma unroll
        for (int nt = 0; nt < 8; nt++) {
            mxA = fmaxf(mxA, fmaxf(s[nt][0], s[nt][1]));
            mxB = fmaxf(mxB, fmaxf(s[nt][2], s[nt][3]));
        }
        mxA = fmaxf(mxA, __shfl_xor_sync(0xffffffffu, mxA, 1));
        mxA = fmaxf(mxA, __shfl_xor_sync(0xffffffffu, mxA, 2));
        mxB = fmaxf(mxB, __shfl_xor_sync(0xffffffffu, mxB, 1));
        mxB = fmaxf(mxB, __shfl_xor_sync(0xffffffffu, mxB, 2));
        float mnA = fmaxf(m[0], mxA), mnB = fmaxf(m[1], mxB);
        float fA = __expf(m[0] - mnA), fB = __expf(m[1] - mnB);
        float sA = 0.f, sB = 0.f;
#pragma unroll
        for (int nt = 0; nt < 8; nt++) {
            s[nt][0] = __expf(s[nt][0] - mnA);
            s[nt][1] = __expf(s[nt][1] - mnA);
            s[nt][2] = __expf(s[nt][2] - mnB);
            s[nt][3] = __expf(s[nt][3] - mnB);
            sA += s[nt][0] + s[nt][1];
            sB += s[nt][2] + s[nt][3];
        }
        sA += __shfl_xor_sync(0xffffffffu, sA, 1);
        sA += __shfl_xor_sync(0xffffffffu, sA, 2);
        sB += __shfl_xor_sync(0xffffffffu, sB, 1);
        sB += __shfl_xor_sync(0xffffffffu, sB, 2);
        l[0] = l[0] * fA + sA; m[0] = mnA;
        l[1] = l[1] * fB + sB; m[1] = mnB;
#pragma unroll
        for (int nt = 0; nt < 8; nt++) {
            o[nt][0] *= fA; o[nt][1] *= fA;
            o[nt][2] *= fB; o[nt][3] *= fB;
        }

        uint32_t pk[4][4];
#pragma unroll
        for (int i = 0; i < 4; i++) {
            pk[i][0] = pack_h2(s[2*i][0],   s[2*i][1]);
            pk[i][1] = pack_h2(s[2*i][2],   s[2*i][3]);
            pk[i][2] = pack_h2(s[2*i+1][0], s[2*i+1][1]);
            pk[i][3] = pack_h2(s[2*i+1][2], s[2*i+1][3]);
        }

        uint32_t vb = kb + 8192;
#pragma unroll
        for (int i = 0; i < 4; i++) {
            int vrow = i * 16 + (lane & 15);
#pragma unroll
            for (int hdp = 0; hdp < 4; hdp++) {
                uint32_t r4[4];
                int c = 2 * hdp + (lane >> 4);
                ldm_x4_t(r4, vb + swzR(vrow, c));
                mma_f16(o[2 * hdp],     pk[i], r4);
                mma_f16(o[2 * hdp + 1], pk[i], r4 + 2);
            }
        }
    }
#undef LOADQ
#undef LOADKV

    float iA = 1.f / l[0], iB = 1.f / l[1];
    size_t rowA = (size_t)(b * SEQ + qt * 64 + wrow + g);
    f16* oA = O + rowA * DM + h * HDIM;
    f16* oB = oA + (size_t)8 * DM;
#pragma unroll
    for (int nt = 0; nt < 8; nt++) {
        int cc = nt * 8 + 2 * tg;
        *(__half2*)(oA + cc) = __floats2half2_rn(o[nt][0] * iA, o[nt][1] * iA);
        *(__half2*)(oB + cc) = __floats2half2_rn(o[nt][2] * iB, o[nt][3] * iB);
    }
}

// -------------------- host orchestration ----------------------------------
#define SM128  (3 * (128 * 128 + 16384))   // 98304
#define SM6464 (3 * (64 * 128 + 8192))     // 49152

extern "C" void kernel_launch(void* const* d_in, const int* in_sizes, int n_in,
                              void* d_out, int out_size) {
    const int*   ctx  = (const int*)  d_in[0];
    const float* tok  = (const float*)d_in[1];
    const float* pos  = (const float*)d_in[2];
    const float* Wq   = (const float*)d_in[3];
    const float* Wk   = (const float*)d_in[4];
    const float* Wv   = (const float*)d_in[5];
    const float* Wo   = (const float*)d_in[6];
    const float* bo   = (const float*)d_in[7];
    const float* ln1g = (const float*)d_in[8];
    const float* ln1b = (const float*)d_in[9];
    const float* W1   = (const float*)d_in[10];
    const float* b1   = (const float*)d_in[11];
    const float* W2   = (const float*)d_in[12];
    const float* b2   = (const float*)d_in[13];
    const float* ln2g = (const float*)d_in[14];
    const float* ln2b = (const float*)d_in[15];
    const float* lnfg = (const float*)d_in[16];
    const float* lnfb = (const float*)d_in[17];
    const float* Wout = (const float*)d_in[18];
    const float* bout = (const float*)d_in[19];

    float* px;
    f16 *pqkv, *ph, *pat, *pff;
    f16 *pwqkv, *pwo, *pw1, *pw2, *pwout;
    cudaGetSymbolAddress((void**)&px,   g_x);
    cudaGetSymbolAddress((void**)&pqkv, g_qkv);
    cudaGetSymbolAddress((void**)&ph,   g_h);
    cudaGetSymbolAddress((void**)&pat,  g_at);
    cudaGetSymbolAddress((void**)&pff,  g_ff);
    cudaGetSymbolAddress((void**)&pwqkv, g_wqkv);
    cudaGetSymbolAddress((void**)&pwo,   g_wo);
    cudaGetSymbolAddress((void**)&pw1,   g_w1);
    cudaGetSymbolAddress((void**)&pw2,   g_w2);
    cudaGetSymbolAddress((void**)&pwout, g_wout);

    cudaFuncSetAttribute(attn_f16,
                         cudaFuncAttributeMaxDynamicSharedMemorySize, ATT_SMEM);
    cudaFuncSetAttribute((const void*)hgemm<128, 128, 2>,
                         cudaFuncAttributeMaxDynamicSharedMemorySize, SM128);
    cudaFuncSetAttribute((const void*)hgemm<64, 64, 3>,
                         cudaFuncAttributeMaxDynamicSharedMemorySize, SM6464);

    // ---- fused weight conversion (single launch) ----
    {
        WCParams p;
        unsigned nQ  = (unsigned)(NL * DM * DM / 16);     // per Q/K/V/Wo
        unsigned nF  = (unsigned)(NL * DM * DFF / 16);    // per W1/W2
        unsigned nO  = (unsigned)(DM * NV / 16);          // Wout
        p.seg[0] = {Wq,   pwqkv, DM,  QKVS, 0};
        p.seg[1] = {Wk,   pwqkv, DM,  QKVS, DM};
        p.seg[2] = {Wv,   pwqkv, DM,  QKVS, 2 * DM};
        p.seg[3] = {Wo,   pwo,   DM,  DM,   0};
        p.seg[4] = {W1,   pw1,   DFF, DFF,  0};
        p.seg[5] = {W2,   pw2,   DM,  DM,   0};
        p.seg[6] = {Wout, pwout, NV,  NV,   0};
        unsigned counts[7] = {nQ, nQ, nQ, nQ, nF, nF, nO};
        unsigned acc = 0;
        for (int i = 0; i < 7; i++) { p.start[i] = acc; acc += counts[i]; }
        p.start[7] = acc;
        wconv_all<<<(acc + 255) / 256, 256>>>(p, acc);
    }

    embed_kernel<<<TOK, 256>>>(ctx, tok, pos);

    for (int l = 0; l < NL; l++) {
        size_t oqkv = (size_t)l * DM * QKVS;
        size_t owo  = (size_t)l * DM * DM;
        size_t ow1  = (size_t)l * DM * DFF;
        size_t ow2  = (size_t)l * DFF * DM;

        ln_half<<<TOK / 8, 256>>>(px, ln1g + l * DM, ln1b + l * DM, ph);
        hgemm<128, 128, 2><<<dim3(16, 18), 256, SM128>>>(
            ph, pwqkv + oqkv, nullptr, nullptr, nullptr, pqkv, QKVS, DM, 0);
        attn_f16<<<dim3(SEQ / 64, NH, 2), 128, ATT_SMEM>>>(pqkv, pat);
        hgemm<64, 64, 3><<<dim3(32, 12), 256, SM6464>>>(
            pat, pwo + owo, bo + l * DM, px, px, nullptr, DM, DM, 0);
        ln_half<<<TOK / 8, 256>>>(px, ln2g + l * DM, ln2b + l * DM, ph);
        hgemm<128, 128, 2><<<dim3(16, 24), 256, SM128>>>(
            ph, pw1 + ow1, b1 + (size_t)l * DFF, nullptr, nullptr, pff,
            DFF, DM, 1);
        hgemm<64, 64, 3><<<dim3(32, 12), 256, SM6464>>>(
            pff, pw2 + ow2, b2 + l * DM, px, px, nullptr, DM, DFF, 0);
    }

    ln_half<<<TOK / 8, 256>>>(px, lnfg, lnfb, ph);
    hgemm<128, 128, 2><<<dim3(16, 250), 256, SM128>>>(
        ph, pwout, bout, nullptr, (float*)d_out, nullptr, NV, DM, 0);
}